// round 8
// baseline (speedup 1.0000x reference)
#include <cuda_runtime.h>
#include <math.h>

#define Bc 4
#define Lc 32
#define Cc 32
#define Hc 128
#define Wc 128
#define HWc (Hc*Wc)
#define IMG_SLICE (Cc*HWc)

// Internal image buffers, channel-interleaved [B,L,H,W,C].
__device__ float g_imgA[(size_t)Bc*Lc*IMG_SLICE];   // transposed input (slice0 read-only) + ping-pong
__device__ float g_imgB[(size_t)Bc*Lc*IMG_SLICE];   // ping-pong
__device__ float g_imgF[(size_t)Bc*Lc*IMG_SLICE];   // finalized slices (HWC gather sources)
// Flow buffers, planar [B,L,2,H,W]
__device__ float g_flowA[(size_t)Bc*Lc*2*HWc];
__device__ float g_flowB[(size_t)Bc*Lc*2*HWc];
__device__ float g_flowF[(size_t)Bc*Lc*2*HWc];

// ---------------------------------------------------------------------------
// CHW -> HWC transpose of all input image slices; also copies slice l==0
// straight to d_out (CHW) on the fly.
__global__ void t_chw2hwc(const float* __restrict__ src, float* __restrict__ dst,
                          float* __restrict__ out) {
    __shared__ float sm[32][65];
    int tile = blockIdx.x & 255;
    int sl   = blockIdx.x >> 8;
    int pix0 = tile * 64;
    const float* s = src + (size_t)sl * IMG_SLICE;
    float*       d = dst + (size_t)sl * IMG_SLICE;
    float*       o = out + (size_t)sl * IMG_SLICE;
    bool isL0 = ((sl & (Lc - 1)) == 0);
    int tx = threadIdx.x & 63, ty = threadIdx.x >> 6;
    #pragma unroll
    for (int i = 0; i < 8; i++) {
        int c = ty + i * 4;
        float v = s[c * HWc + pix0 + tx];
        sm[c][tx] = v;
        if (isL0) o[c * HWc + pix0 + tx] = v;
    }
    __syncthreads();
    #pragma unroll
    for (int j = 0; j < 2; j++) {
        int u = threadIdx.x + j * 256;
        int p = u >> 3, q = u & 7;
        float4 v = make_float4(sm[4*q+0][p], sm[4*q+1][p], sm[4*q+2][p], sm[4*q+3][p]);
        *(float4*)(d + (size_t)(pix0 + p) * Cc + 4 * q) = v;
    }
}

// ---------------------------------------------------------------------------
// Grid/weight computation — VERBATIM the numerics that passed (R2/R5).
__device__ __forceinline__ void grid_weights(
    int pix, float qfx, float qfy,
    float& w00, float& w01, float& w10, float& w11,
    int& o00, int& o01, int& o10, int& o11)
{
    int h = pix >> 7;
    int w = pix & (Wc - 1);
    float gx = -1.0f + (2.0f / Wc) * ((float)w + 0.5f);
    float gy = -1.0f + (2.0f / Hc) * ((float)h + 0.5f);
    float fx = gx + qfx;
    float t  = fx + 1.0f;
    fx = t - 2.0f * floorf(t * 0.5f) - 1.0f;   // remainder(fx+1,2)-1 (x wrap)
    float fy = gy + qfy;

    float x = (fx + 1.0f) * (Wc * 0.5f) - 0.5f;
    float y = (fy + 1.0f) * (Hc * 0.5f) - 0.5f;
    float x0f = floorf(x), y0f = floorf(y);
    float tx = x - x0f, ty = y - y0f;
    int x0 = (int)x0f, y0 = (int)y0f;
    int x1 = x0 + 1,  y1 = y0 + 1;

    float vx0 = (x0 >= 0 && x0 < Wc) ? 1.0f : 0.0f;
    float vx1 = (x1 >= 0 && x1 < Wc) ? 1.0f : 0.0f;
    float vy0 = (y0 >= 0 && y0 < Hc) ? 1.0f : 0.0f;
    float vy1 = (y1 >= 0 && y1 < Hc) ? 1.0f : 0.0f;

    w00 = (1.0f - tx) * (1.0f - ty) * vx0 * vy0;
    w01 = tx * (1.0f - ty) * vx1 * vy0;
    w10 = (1.0f - tx) * ty * vx0 * vy1;
    w11 = tx * ty * vx1 * vy1;

    int cx0 = min(max(x0, 0), Wc - 1), cx1 = min(max(x1, 0), Wc - 1);
    int cy0 = min(max(y0, 0), Hc - 1), cy1 = min(max(y1, 0), Hc - 1);
    o00 = cy0 * Wc + cx0; o01 = cy0 * Wc + cx1;
    o10 = cy1 * Wc + cx0; o11 = cy1 * Wc + cx1;
}

// ---------------------------------------------------------------------------
// Fused image+flow compose. R5 body: warp = 4 pixels x 8 channel-groups,
// block = 32 pixels, grid = (HW/32, Lp, B). Lanes c4<2 additionally compose
// the flow (same weights/offsets). Finalized image slices: smem-staged
// coalesced CHW stores direct to d_out; HWC copy kept while still a gather
// source (finHWC).
__global__ void __launch_bounds__(256) compose_fused(int step, int finHWC, int doFlow,
    const float* __restrict__ srcImg, const float* __restrict__ orgImg,
    float* __restrict__ finImg,       float* __restrict__ dstImg,
    const float* __restrict__ srcFlow, const float* __restrict__ orgFlow,
    float* __restrict__ finFlow,       float* __restrict__ dstFlow,
    float* __restrict__ outImg)
{
    __shared__ float sm[32 * 33];
    int t   = threadIdx.x;
    int c4  = t & 7;
    int pl  = t >> 3;                 // pixel-local 0..31
    int pix = blockIdx.x * 32 + pl;
    int lp  = blockIdx.y;
    int b   = blockIdx.z;
    int l   = step + lp;

    const float* cf = srcFlow + (b * Lc + l) * (2 * HWc);
    float qfx = __ldg(cf + pix);
    float qfy = __ldg(cf + HWc + pix);

    float w00, w01, w10, w11; int o00, o01, o10, o11;
    grid_weights(pix, qfx, qfy, w00, w01, w10, w11, o00, o01, o10, o11);

    int co = c4 * 4;
    const float* pi = ((lp == 0) ? orgImg : (lp < step) ? finImg : srcImg)
                      + (b * Lc + lp) * IMG_SLICE;
    float4 t00 = __ldg((const float4*)(pi + o00 * Cc + co));
    float4 t01 = __ldg((const float4*)(pi + o01 * Cc + co));
    float4 t10 = __ldg((const float4*)(pi + o10 * Cc + co));
    float4 t11 = __ldg((const float4*)(pi + o11 * Cc + co));

    int sliceOff = (b * Lc + l) * IMG_SLICE;
    int hwcOff   = sliceOff + pix * Cc + co;
    float4 cv = __ldg((const float4*)(srcImg + hwcOff));

    // fused flow compose: lanes c4 in {0,1} handle flow channel c4 of pixel pl
    if (doFlow && c4 < 2) {
        const float* pf = ((lp == 0) ? orgFlow
                         : (lp < step) ? finFlow : srcFlow)
                          + (b * Lc + lp) * (2 * HWc) + c4 * HWc;
        float sf = w00 * __ldg(pf + o00) + w01 * __ldg(pf + o01)
                 + w10 * __ldg(pf + o10) + w11 * __ldg(pf + o11);
        float* df = ((l < 2 * step) ? finFlow : dstFlow) + (b * Lc + l) * (2 * HWc);
        float q = (c4 == 0) ? qfx : qfy;
        df[c4 * HWc + pix] = q + sf;
    }

    float4 r;
    r.x = cv.x + w00 * t00.x + w01 * t01.x + w10 * t10.x + w11 * t11.x;
    r.y = cv.y + w00 * t00.y + w01 * t01.y + w10 * t10.y + w11 * t11.y;
    r.z = cv.z + w00 * t00.z + w01 * t01.z + w10 * t10.z + w11 * t11.z;
    r.w = cv.w + w00 * t00.w + w01 * t01.w + w10 * t10.w + w11 * t11.w;

    if (l < 2 * step) {                         // finalized (block-uniform)
        if (finHWC) *(float4*)(finImg + hwcOff) = r;
        int sb = pl * 33 + co;
        sm[sb + 0] = r.x; sm[sb + 1] = r.y; sm[sb + 2] = r.z; sm[sb + 3] = r.w;
        __syncthreads();
        int lane = t & 31, wp = t >> 5;
        float* oC = outImg + sliceOff + blockIdx.x * 32 + lane;
        #pragma unroll
        for (int i = 0; i < 4; i++) {
            int ch = wp * 4 + i;
            __stcs(oC + ch * HWc, sm[lane * 33 + ch]);
        }
    } else {
        *(float4*)(dstImg + hwcOff) = r;
    }
}

// ---------------------------------------------------------------------------
extern "C" void kernel_launch(void* const* d_in, const int* in_sizes, int n_in,
                              void* d_out, int out_size) {
    const float* flows  = (const float*)d_in[0];
    const float* images = (const float*)d_in[1];
    if (n_in >= 2 && in_sizes[0] > in_sizes[1]) {
        const float* tmp = flows; flows = images; images = tmp;
    }
    float* out = (float*)d_out;

    float *iA, *iB, *iF, *fA, *fB, *fF;
    cudaGetSymbolAddress((void**)&iA, g_imgA);
    cudaGetSymbolAddress((void**)&iB, g_imgB);
    cudaGetSymbolAddress((void**)&iF, g_imgF);
    cudaGetSymbolAddress((void**)&fA, g_flowA);
    cudaGetSymbolAddress((void**)&fB, g_flowB);
    cudaGetSymbolAddress((void**)&fF, g_flowF);

    // 1) transpose input images CHW -> HWC into iA (+ slice0 -> d_out)
    t_chw2hwc<<<Bc * Lc * 256, 256>>>(images, iA, out);

    // 2) log-scan, flow fused into image kernel
    const float* sImg  = iA;    float* dImg  = iB;
    const float* sFlow = flows; float* dFlow = fB;
    for (int s = 1; s < Lc; s <<= 1) {
        int Lp = Lc - s;
        int doFlow = (s < 16) ? 1 : 0;   // last step's flow output never consumed
        int finHWC = (s < 16) ? 1 : 0;   // last step's finalized slices never re-gathered
        dim3 gi(HWc / 32, Lp, Bc);
        compose_fused<<<gi, 256>>>(s, finHWC, doFlow,
                                   sImg, iA, iF, dImg,
                                   sFlow, flows, fF, dFlow, out);

        const float* tI = sImg; sImg = dImg; dImg = (float*)tI;
        if (s == 1) { sFlow = fB; dFlow = fA; }
        else { const float* tF = sFlow; sFlow = dFlow; dFlow = (float*)tF; }
    }
}

// round 9
// speedup vs baseline: 1.2072x; 1.2072x over previous
#include <cuda_runtime.h>
#include <math.h>

#define Bc 4
#define Lc 32
#define Cc 32
#define Hc 128
#define Wc 128
#define HWc (Hc*Wc)
#define IMG_SLICE (Cc*HWc)

// Internal image buffers, channel-interleaved [B,L,H,W,C].
__device__ float g_imgA[(size_t)Bc*Lc*IMG_SLICE];   // transposed input (slice0 read-only) + ping-pong
__device__ float g_imgB[(size_t)Bc*Lc*IMG_SLICE];   // ping-pong
__device__ float g_imgF[(size_t)Bc*Lc*IMG_SLICE];   // finalized slices (HWC gather sources)
// Flow buffers, planar [B,L,2,H,W]
__device__ float g_flowA[(size_t)Bc*Lc*2*HWc];
__device__ float g_flowB[(size_t)Bc*Lc*2*HWc];
__device__ float g_flowF[(size_t)Bc*Lc*2*HWc];

// ---------------------------------------------------------------------------
// CHW -> HWC transpose of all input image slices into g_imgA; also copies
// slice l==0 straight to d_out (CHW) on the fly.
__global__ void t_chw2hwc(const float* __restrict__ src, float* __restrict__ out) {
    __shared__ float sm[32][65];
    int tile = blockIdx.x & 255;
    int sl   = blockIdx.x >> 8;
    int pix0 = tile * 64;
    const float* s = src + (size_t)sl * IMG_SLICE;
    float*       d = g_imgA + (size_t)sl * IMG_SLICE;
    float*       o = out + (size_t)sl * IMG_SLICE;
    bool isL0 = ((sl & (Lc - 1)) == 0);
    int tx = threadIdx.x & 63, ty = threadIdx.x >> 6;
    #pragma unroll
    for (int i = 0; i < 8; i++) {
        int c = ty + i * 4;
        float v = s[c * HWc + pix0 + tx];
        sm[c][tx] = v;
        if (isL0) o[c * HWc + pix0 + tx] = v;
    }
    __syncthreads();
    #pragma unroll
    for (int j = 0; j < 2; j++) {
        int u = threadIdx.x + j * 256;
        int p = u >> 3, q = u & 7;
        float4 v = make_float4(sm[4*q+0][p], sm[4*q+1][p], sm[4*q+2][p], sm[4*q+3][p]);
        *(float4*)(d + (size_t)(pix0 + p) * Cc + 4 * q) = v;
    }
}

// ---------------------------------------------------------------------------
// Grid/weight computation — VERBATIM the numerics that passed (R2/R5).
__device__ __forceinline__ void grid_weights(
    int pix, float qfx, float qfy,
    float& w00, float& w01, float& w10, float& w11,
    int& o00, int& o01, int& o10, int& o11)
{
    int h = pix >> 7;
    int w = pix & (Wc - 1);
    float gx = -1.0f + (2.0f / Wc) * ((float)w + 0.5f);
    float gy = -1.0f + (2.0f / Hc) * ((float)h + 0.5f);
    float fx = gx + qfx;
    float t  = fx + 1.0f;
    fx = t - 2.0f * floorf(t * 0.5f) - 1.0f;   // remainder(fx+1,2)-1 (x wrap)
    float fy = gy + qfy;

    float x = (fx + 1.0f) * (Wc * 0.5f) - 0.5f;
    float y = (fy + 1.0f) * (Hc * 0.5f) - 0.5f;
    float x0f = floorf(x), y0f = floorf(y);
    float tx = x - x0f, ty = y - y0f;
    int x0 = (int)x0f, y0 = (int)y0f;
    int x1 = x0 + 1,  y1 = y0 + 1;

    float vx0 = (x0 >= 0 && x0 < Wc) ? 1.0f : 0.0f;
    float vx1 = (x1 >= 0 && x1 < Wc) ? 1.0f : 0.0f;
    float vy0 = (y0 >= 0 && y0 < Hc) ? 1.0f : 0.0f;
    float vy1 = (y1 >= 0 && y1 < Hc) ? 1.0f : 0.0f;

    w00 = (1.0f - tx) * (1.0f - ty) * vx0 * vy0;
    w01 = tx * (1.0f - ty) * vx1 * vy0;
    w10 = (1.0f - tx) * ty * vx0 * vy1;
    w11 = tx * ty * vx1 * vy1;

    int cx0 = min(max(x0, 0), Wc - 1), cx1 = min(max(x1, 0), Wc - 1);
    int cy0 = min(max(y0, 0), Hc - 1), cy1 = min(max(y1, 0), Hc - 1);
    o00 = cy0 * Wc + cx0; o01 = cy0 * Wc + cx1;
    o10 = cy1 * Wc + cx0; o11 = cy1 * Wc + cx1;
}

// flowSel: 0 = runtime input flows, 1 = g_flowA, 2 = g_flowB
__device__ __forceinline__ const float* flow_sel(int sel, const float* flows) {
    return (sel == 0) ? flows : (sel == 1) ? (const float*)g_flowA : (const float*)g_flowB;
}

// ---------------------------------------------------------------------------
// Flow compose (planar). grid = (HW/256, Lp, B).
__global__ void __launch_bounds__(256) compose_flow(int step, int srcSel, int dstSel,
    const float* __restrict__ flows)
{
    int pix = blockIdx.x * 256 + threadIdx.x;
    int lp  = blockIdx.y;
    int b   = blockIdx.z;
    int l   = step + lp;

    const float* srcFlow = flow_sel(srcSel, flows);
    const float* cf = srcFlow + (b * Lc + l) * (2 * HWc);
    float qfx = __ldg(cf + pix);
    float qfy = __ldg(cf + HWc + pix);

    float w00, w01, w10, w11; int o00, o01, o10, o11;
    grid_weights(pix, qfx, qfy, w00, w01, w10, w11, o00, o01, o10, o11);

    const float* pf = (lp == 0) ? (flows + (b * Lc) * (2 * HWc))
                   : (lp < step) ? ((const float*)g_flowF + (b * Lc + lp) * (2 * HWc))
                                 : (srcFlow + (b * Lc + lp) * (2 * HWc));
    float* dstFlow = (dstSel == 1) ? g_flowA : g_flowB;
    float* df = ((l < 2 * step) ? g_flowF : dstFlow) + (b * Lc + l) * (2 * HWc);

    float s0 = w00 * __ldg(pf + o00) + w01 * __ldg(pf + o01)
             + w10 * __ldg(pf + o10) + w11 * __ldg(pf + o11);
    const float* pf1 = pf + HWc;
    float s1 = w00 * __ldg(pf1 + o00) + w01 * __ldg(pf1 + o01)
             + w10 * __ldg(pf1 + o10) + w11 * __ldg(pf1 + o11);
    df[pix]       = qfx + s0;
    df[HWc + pix] = qfy + s1;
}

// ---------------------------------------------------------------------------
// Image compose — R5 body. Warp = 4 pixels x 8 channel-groups (1 L1 wavefront
// per pixel-tap). Block = 32 pixels. grid = (HW/32, Lp, B).
// imgPar: 0 -> src=g_imgA,dst=g_imgB; 1 -> src=g_imgB,dst=g_imgA.
// Finalized slices: smem-staged coalesced CHW stores direct to d_out;
// HWC copy kept only while still a gather source (finHWC).
__global__ void __launch_bounds__(256) compose_img3(int step, int finHWC,
    int imgPar, int flowSrcSel,
    const float* __restrict__ flows, float* __restrict__ outImg)
{
    __shared__ float sm[32 * 33];
    int t   = threadIdx.x;
    int c4  = t & 7;
    int pl  = t >> 3;                 // pixel-local 0..31
    int pix = blockIdx.x * 32 + pl;
    int lp  = blockIdx.y;
    int b   = blockIdx.z;
    int l   = step + lp;

    const float* srcImg = imgPar ? (const float*)g_imgB : (const float*)g_imgA;
    float*       dstImg = imgPar ? g_imgA : g_imgB;

    const float* cf = flow_sel(flowSrcSel, flows) + (b * Lc + l) * (2 * HWc);
    float qfx = __ldg(cf + pix);
    float qfy = __ldg(cf + HWc + pix);

    float w00, w01, w10, w11; int o00, o01, o10, o11;
    grid_weights(pix, qfx, qfy, w00, w01, w10, w11, o00, o01, o10, o11);

    int co = c4 * 4;
    const float* pi = ((lp == 0) ? (const float*)g_imgA
                     : (lp < step) ? (const float*)g_imgF : srcImg)
                      + (b * Lc + lp) * IMG_SLICE;
    float4 t00 = __ldg((const float4*)(pi + o00 * Cc + co));
    float4 t01 = __ldg((const float4*)(pi + o01 * Cc + co));
    float4 t10 = __ldg((const float4*)(pi + o10 * Cc + co));
    float4 t11 = __ldg((const float4*)(pi + o11 * Cc + co));

    int sliceOff = (b * Lc + l) * IMG_SLICE;
    int hwcOff   = sliceOff + pix * Cc + co;
    float4 cv = __ldg((const float4*)(srcImg + hwcOff));

    float4 r;
    r.x = cv.x + w00 * t00.x + w01 * t01.x + w10 * t10.x + w11 * t11.x;
    r.y = cv.y + w00 * t00.y + w01 * t01.y + w10 * t10.y + w11 * t11.y;
    r.z = cv.z + w00 * t00.z + w01 * t01.z + w10 * t10.z + w11 * t11.z;
    r.w = cv.w + w00 * t00.w + w01 * t01.w + w10 * t10.w + w11 * t11.w;

    if (l < 2 * step) {                         // finalized (block-uniform)
        if (finHWC) *(float4*)(g_imgF + hwcOff) = r;
        int sb = pl * 33 + co;
        sm[sb + 0] = r.x; sm[sb + 1] = r.y; sm[sb + 2] = r.z; sm[sb + 3] = r.w;
        __syncthreads();
        int lane = t & 31, wp = t >> 5;
        float* oC = outImg + sliceOff + blockIdx.x * 32 + lane;
        #pragma unroll
        for (int i = 0; i < 4; i++) {
            int ch = wp * 4 + i;
            __stcs(oC + ch * HWc, sm[lane * 33 + ch]);
        }
    } else {
        *(float4*)(dstImg + hwcOff) = r;
    }
}

// ---------------------------------------------------------------------------
extern "C" void kernel_launch(void* const* d_in, const int* in_sizes, int n_in,
                              void* d_out, int out_size) {
    const float* flows  = (const float*)d_in[0];
    const float* images = (const float*)d_in[1];
    if (n_in >= 2 && in_sizes[0] > in_sizes[1]) {
        const float* tmp = flows; flows = images; images = tmp;
    }
    float* out = (float*)d_out;

    // 1) transpose input images CHW -> HWC into g_imgA (+ slice0 -> d_out)
    t_chw2hwc<<<Bc * Lc * 256, 256>>>(images, out);

    // 2) log-scan.
    // Image parity per step s=1,2,4,8,16: src = A,B,A,B,A -> imgPar 0,1,0,1,0
    // Flow buffers: s=1 src=input(0) dst=B(2); s=2 src=B(2) dst=A(1);
    //               s=4 src=A(1) dst=B(2); s=8 src=B(2) dst=A(1); s=16 src=A(1)
    int imgPar = 0;
    int flowSrc = 0;
    for (int s = 1; s < Lc; s <<= 1) {
        int Lp = Lc - s;
        int flowDst = (flowSrc == 2) ? 1 : 2;   // alternate; s=1: 0 -> 2

        if (s < 16) {  // last step's flow output is never consumed
            dim3 gf(HWc / 256, Lp, Bc);
            compose_flow<<<gf, 256>>>(s, flowSrc, flowDst, flows);
        }
        int finHWC = (s < 16) ? 1 : 0;  // last step's finalized slices never re-gathered
        dim3 gi(HWc / 32, Lp, Bc);
        compose_img3<<<gi, 256>>>(s, finHWC, imgPar, flowSrc, flows, out);

        imgPar ^= 1;
        flowSrc = flowDst;
    }
}

// round 10
// speedup vs baseline: 1.2459x; 1.0320x over previous
#include <cuda_runtime.h>
#include <math.h>

#define Bc 4
#define Lc 32
#define Cc 32
#define Hc 128
#define Wc 128
#define HWc (Hc*Wc)
#define IMG_SLICE (Cc*HWc)
#define IMG_BLKS (HWc/32)     // 512 image blocks per (lp,b)
#define FLOW_BLKS (HWc/256)   // 64 flow blocks per (lp,b)

// Internal image buffers, channel-interleaved [B,L,H,W,C].
__device__ float g_imgA[(size_t)Bc*Lc*IMG_SLICE];   // transposed input (slice0 read-only) + ping-pong
__device__ float g_imgB[(size_t)Bc*Lc*IMG_SLICE];   // ping-pong
__device__ float g_imgF[(size_t)Bc*Lc*IMG_SLICE];   // finalized slices (HWC gather sources)
// Flow buffers, planar [B,L,2,H,W]
__device__ float g_flowA[(size_t)Bc*Lc*2*HWc];
__device__ float g_flowB[(size_t)Bc*Lc*2*HWc];
__device__ float g_flowF[(size_t)Bc*Lc*2*HWc];

// ---------------------------------------------------------------------------
// CHW -> HWC transpose of all input image slices into g_imgA; also copies
// slice l==0 straight to d_out (CHW) on the fly.
__global__ void t_chw2hwc(const float* __restrict__ src, float* __restrict__ out) {
    __shared__ float sm[32][65];
    int tile = blockIdx.x & 255;
    int sl   = blockIdx.x >> 8;
    int pix0 = tile * 64;
    const float* s = src + (size_t)sl * IMG_SLICE;
    float*       d = g_imgA + (size_t)sl * IMG_SLICE;
    float*       o = out + (size_t)sl * IMG_SLICE;
    bool isL0 = ((sl & (Lc - 1)) == 0);
    int tx = threadIdx.x & 63, ty = threadIdx.x >> 6;
    #pragma unroll
    for (int i = 0; i < 8; i++) {
        int c = ty + i * 4;
        float v = s[c * HWc + pix0 + tx];
        sm[c][tx] = v;
        if (isL0) o[c * HWc + pix0 + tx] = v;
    }
    __syncthreads();
    #pragma unroll
    for (int j = 0; j < 2; j++) {
        int u = threadIdx.x + j * 256;
        int p = u >> 3, q = u & 7;
        float4 v = make_float4(sm[4*q+0][p], sm[4*q+1][p], sm[4*q+2][p], sm[4*q+3][p]);
        *(float4*)(d + (size_t)(pix0 + p) * Cc + 4 * q) = v;
    }
}

// ---------------------------------------------------------------------------
// Grid/weight computation — VERBATIM the numerics that passed (R2/R5).
__device__ __forceinline__ void grid_weights(
    int pix, float qfx, float qfy,
    float& w00, float& w01, float& w10, float& w11,
    int& o00, int& o01, int& o10, int& o11)
{
    int h = pix >> 7;
    int w = pix & (Wc - 1);
    float gx = -1.0f + (2.0f / Wc) * ((float)w + 0.5f);
    float gy = -1.0f + (2.0f / Hc) * ((float)h + 0.5f);
    float fx = gx + qfx;
    float t  = fx + 1.0f;
    fx = t - 2.0f * floorf(t * 0.5f) - 1.0f;   // remainder(fx+1,2)-1 (x wrap)
    float fy = gy + qfy;

    float x = (fx + 1.0f) * (Wc * 0.5f) - 0.5f;
    float y = (fy + 1.0f) * (Hc * 0.5f) - 0.5f;
    float x0f = floorf(x), y0f = floorf(y);
    float tx = x - x0f, ty = y - y0f;
    int x0 = (int)x0f, y0 = (int)y0f;
    int x1 = x0 + 1,  y1 = y0 + 1;

    float vx0 = (x0 >= 0 && x0 < Wc) ? 1.0f : 0.0f;
    float vx1 = (x1 >= 0 && x1 < Wc) ? 1.0f : 0.0f;
    float vy0 = (y0 >= 0 && y0 < Hc) ? 1.0f : 0.0f;
    float vy1 = (y1 >= 0 && y1 < Hc) ? 1.0f : 0.0f;

    w00 = (1.0f - tx) * (1.0f - ty) * vx0 * vy0;
    w01 = tx * (1.0f - ty) * vx1 * vy0;
    w10 = (1.0f - tx) * ty * vx0 * vy1;
    w11 = tx * ty * vx1 * vy1;

    int cx0 = min(max(x0, 0), Wc - 1), cx1 = min(max(x1, 0), Wc - 1);
    int cy0 = min(max(y0, 0), Hc - 1), cy1 = min(max(y1, 0), Hc - 1);
    o00 = cy0 * Wc + cx0; o01 = cy0 * Wc + cx1;
    o10 = cy1 * Wc + cx0; o11 = cy1 * Wc + cx1;
}

// flowSel: 0 = runtime input flows, 1 = g_flowA, 2 = g_flowB
__device__ __forceinline__ const float* flow_sel(int sel, const float* flows) {
    return (sel == 0) ? flows : (sel == 1) ? (const float*)g_flowA : (const float*)g_flowB;
}

// ---------------------------------------------------------------------------
// Fused step kernel with BLOCK-level specialization:
//   blockIdx.x <  IMG_BLKS               : image compose (R5 body, untouched)
//   blockIdx.x >= IMG_BLKS (64 blocks)   : flow compose (R9 body, untouched)
// grid = (IMG_BLKS [+FLOW_BLKS], Lp, B). Both paths read only step-s flow and
// write disjoint buffers, so they can run concurrently in one launch.
__global__ void __launch_bounds__(256) compose_step(int step, int finHWC,
    int imgPar, int flowSrcSel, int flowDstSel,
    const float* __restrict__ flows, float* __restrict__ outImg)
{
    int lp = blockIdx.y;
    int b  = blockIdx.z;
    int l  = step + lp;
    const float* srcFlow = flow_sel(flowSrcSel, flows);

    if (blockIdx.x >= IMG_BLKS) {
        // ---------------- flow path ----------------
        int pix = (blockIdx.x - IMG_BLKS) * 256 + threadIdx.x;

        const float* cf = srcFlow + (b * Lc + l) * (2 * HWc);
        float qfx = __ldg(cf + pix);
        float qfy = __ldg(cf + HWc + pix);

        float w00, w01, w10, w11; int o00, o01, o10, o11;
        grid_weights(pix, qfx, qfy, w00, w01, w10, w11, o00, o01, o10, o11);

        const float* pf = (lp == 0) ? (flows + (b * Lc) * (2 * HWc))
                       : (lp < step) ? ((const float*)g_flowF + (b * Lc + lp) * (2 * HWc))
                                     : (srcFlow + (b * Lc + lp) * (2 * HWc));
        float* dstFlow = (flowDstSel == 1) ? g_flowA : g_flowB;
        float* df = ((l < 2 * step) ? g_flowF : dstFlow) + (b * Lc + l) * (2 * HWc);

        float s0 = w00 * __ldg(pf + o00) + w01 * __ldg(pf + o01)
                 + w10 * __ldg(pf + o10) + w11 * __ldg(pf + o11);
        const float* pf1 = pf + HWc;
        float s1 = w00 * __ldg(pf1 + o00) + w01 * __ldg(pf1 + o01)
                 + w10 * __ldg(pf1 + o10) + w11 * __ldg(pf1 + o11);
        df[pix]       = qfx + s0;
        df[HWc + pix] = qfy + s1;
        return;
    }

    // ---------------- image path (R5 body) ----------------
    __shared__ float sm[32 * 33];
    int t   = threadIdx.x;
    int c4  = t & 7;
    int pl  = t >> 3;                 // pixel-local 0..31
    int pix = blockIdx.x * 32 + pl;

    const float* srcImg = imgPar ? (const float*)g_imgB : (const float*)g_imgA;
    float*       dstImg = imgPar ? g_imgA : g_imgB;

    const float* cf = srcFlow + (b * Lc + l) * (2 * HWc);
    float qfx = __ldg(cf + pix);
    float qfy = __ldg(cf + HWc + pix);

    float w00, w01, w10, w11; int o00, o01, o10, o11;
    grid_weights(pix, qfx, qfy, w00, w01, w10, w11, o00, o01, o10, o11);

    int co = c4 * 4;
    const float* pi = ((lp == 0) ? (const float*)g_imgA
                     : (lp < step) ? (const float*)g_imgF : srcImg)
                      + (b * Lc + lp) * IMG_SLICE;
    float4 t00 = __ldg((const float4*)(pi + o00 * Cc + co));
    float4 t01 = __ldg((const float4*)(pi + o01 * Cc + co));
    float4 t10 = __ldg((const float4*)(pi + o10 * Cc + co));
    float4 t11 = __ldg((const float4*)(pi + o11 * Cc + co));

    int sliceOff = (b * Lc + l) * IMG_SLICE;
    int hwcOff   = sliceOff + pix * Cc + co;
    float4 cv = __ldg((const float4*)(srcImg + hwcOff));

    float4 r;
    r.x = cv.x + w00 * t00.x + w01 * t01.x + w10 * t10.x + w11 * t11.x;
    r.y = cv.y + w00 * t00.y + w01 * t01.y + w10 * t10.y + w11 * t11.y;
    r.z = cv.z + w00 * t00.z + w01 * t01.z + w10 * t10.z + w11 * t11.z;
    r.w = cv.w + w00 * t00.w + w01 * t01.w + w10 * t10.w + w11 * t11.w;

    if (l < 2 * step) {                         // finalized (block-uniform)
        if (finHWC) *(float4*)(g_imgF + hwcOff) = r;
        int sb = pl * 33 + co;
        sm[sb + 0] = r.x; sm[sb + 1] = r.y; sm[sb + 2] = r.z; sm[sb + 3] = r.w;
        __syncthreads();
        int lane = t & 31, wp = t >> 5;
        float* oC = outImg + sliceOff + blockIdx.x * 32 + lane;
        #pragma unroll
        for (int i = 0; i < 4; i++) {
            int ch = wp * 4 + i;
            __stcs(oC + ch * HWc, sm[lane * 33 + ch]);
        }
    } else {
        *(float4*)(dstImg + hwcOff) = r;
    }
}

// ---------------------------------------------------------------------------
extern "C" void kernel_launch(void* const* d_in, const int* in_sizes, int n_in,
                              void* d_out, int out_size) {
    const float* flows  = (const float*)d_in[0];
    const float* images = (const float*)d_in[1];
    if (n_in >= 2 && in_sizes[0] > in_sizes[1]) {
        const float* tmp = flows; flows = images; images = tmp;
    }
    float* out = (float*)d_out;

    // 1) transpose input images CHW -> HWC into g_imgA (+ slice0 -> d_out)
    t_chw2hwc<<<Bc * Lc * 256, 256>>>(images, out);

    // 2) log-scan, one fused launch per step (image blocks + flow blocks).
    // Image parity per step s=1,2,4,8,16: src = A,B,A,B,A -> imgPar 0,1,0,1,0
    // Flow buffers: s=1 src=input(0) dst=B(2); then alternate B<->A.
    int imgPar = 0;
    int flowSrc = 0;
    for (int s = 1; s < Lc; s <<= 1) {
        int Lp = Lc - s;
        int flowDst = (flowSrc == 2) ? 1 : 2;
        int doFlow = (s < 16) ? 1 : 0;   // last step's flow output never consumed
        int finHWC = (s < 16) ? 1 : 0;   // last step's finalized slices never re-gathered

        dim3 gi(IMG_BLKS + (doFlow ? FLOW_BLKS : 0), Lp, Bc);
        compose_step<<<gi, 256>>>(s, finHWC, imgPar, flowSrc, flowDst, flows, out);

        imgPar ^= 1;
        flowSrc = flowDst;
    }
}

// round 11
// speedup vs baseline: 1.9024x; 1.5270x over previous
#include <cuda_runtime.h>
#include <cuda_fp16.h>
#include <math.h>

#define Bc 4
#define Lc 32
#define Cc 32
#define Hc 128
#define Wc 128
#define HWc (Hc*Wc)
#define IMG_SLICE (Cc*HWc)          // fp32 elements per image slice (d_out)
#define IMG_SLICE_H (Cc*HWc)        // fp16 elements per internal slice
#define IMG_BLKS (HWc/64)           // 256 image blocks per (lp,b), 64 px each
#define FLOW_BLKS (HWc/256)         // 64 flow blocks per (lp,b)

// Internal image buffers, channel-interleaved [B,L,H,W,C], fp16 (uint4 for 16B align).
__device__ uint4 g_imgA4[(size_t)Bc*Lc*IMG_SLICE_H/8];   // transposed input + ping-pong
__device__ uint4 g_imgB4[(size_t)Bc*Lc*IMG_SLICE_H/8];   // ping-pong
__device__ uint4 g_imgF4[(size_t)Bc*Lc*IMG_SLICE_H/8];   // finalized gather sources
// Flow buffers, planar [B,L,2,H,W], fp32 (precision-critical: feeds coordinates)
__device__ float g_flowA[(size_t)Bc*Lc*2*HWc];
__device__ float g_flowB[(size_t)Bc*Lc*2*HWc];
__device__ float g_flowF[(size_t)Bc*Lc*2*HWc];

union H8 { uint4 u; __half2 h[4]; };

// ---------------------------------------------------------------------------
// CHW(fp32) -> HWC(fp16) transpose of all input image slices into g_imgA;
// also copies slice l==0 straight to d_out (CHW fp32) on the fly.
__global__ void t_chw2hwc(const float* __restrict__ src, float* __restrict__ out) {
    __shared__ float sm[32][65];
    int tile = blockIdx.x & 255;
    int sl   = blockIdx.x >> 8;
    int pix0 = tile * 64;
    const float* s = src + (size_t)sl * IMG_SLICE;
    __half*      d = (__half*)g_imgA4 + (size_t)sl * IMG_SLICE_H;
    float*       o = out + (size_t)sl * IMG_SLICE;
    bool isL0 = ((sl & (Lc - 1)) == 0);
    int tx = threadIdx.x & 63, ty = threadIdx.x >> 6;
    #pragma unroll
    for (int i = 0; i < 8; i++) {
        int c = ty + i * 4;
        float v = s[c * HWc + pix0 + tx];
        sm[c][tx] = v;
        if (isL0) o[c * HWc + pix0 + tx] = v;
    }
    __syncthreads();
    // each thread packs 8 channels of one pixel into a uint4 (8 halves)
    int p = threadIdx.x >> 2, q = threadIdx.x & 3;
    H8 v;
    #pragma unroll
    for (int j = 0; j < 4; j++)
        v.h[j] = __floats2half2_rn(sm[8*q + 2*j][p], sm[8*q + 2*j + 1][p]);
    *(uint4*)(d + (pix0 + p) * Cc + q * 8) = v.u;
}

// ---------------------------------------------------------------------------
// Grid/weight computation — VERBATIM the numerics that passed (R2/R5/R10).
__device__ __forceinline__ void grid_weights(
    int pix, float qfx, float qfy,
    float& w00, float& w01, float& w10, float& w11,
    int& o00, int& o01, int& o10, int& o11)
{
    int h = pix >> 7;
    int w = pix & (Wc - 1);
    float gx = -1.0f + (2.0f / Wc) * ((float)w + 0.5f);
    float gy = -1.0f + (2.0f / Hc) * ((float)h + 0.5f);
    float fx = gx + qfx;
    float t  = fx + 1.0f;
    fx = t - 2.0f * floorf(t * 0.5f) - 1.0f;   // remainder(fx+1,2)-1 (x wrap)
    float fy = gy + qfy;

    float x = (fx + 1.0f) * (Wc * 0.5f) - 0.5f;
    float y = (fy + 1.0f) * (Hc * 0.5f) - 0.5f;
    float x0f = floorf(x), y0f = floorf(y);
    float tx = x - x0f, ty = y - y0f;
    int x0 = (int)x0f, y0 = (int)y0f;
    int x1 = x0 + 1,  y1 = y0 + 1;

    float vx0 = (x0 >= 0 && x0 < Wc) ? 1.0f : 0.0f;
    float vx1 = (x1 >= 0 && x1 < Wc) ? 1.0f : 0.0f;
    float vy0 = (y0 >= 0 && y0 < Hc) ? 1.0f : 0.0f;
    float vy1 = (y1 >= 0 && y1 < Hc) ? 1.0f : 0.0f;

    w00 = (1.0f - tx) * (1.0f - ty) * vx0 * vy0;
    w01 = tx * (1.0f - ty) * vx1 * vy0;
    w10 = (1.0f - tx) * ty * vx0 * vy1;
    w11 = tx * ty * vx1 * vy1;

    int cx0 = min(max(x0, 0), Wc - 1), cx1 = min(max(x1, 0), Wc - 1);
    int cy0 = min(max(y0, 0), Hc - 1), cy1 = min(max(y1, 0), Hc - 1);
    o00 = cy0 * Wc + cx0; o01 = cy0 * Wc + cx1;
    o10 = cy1 * Wc + cx0; o11 = cy1 * Wc + cx1;
}

// flowSel: 0 = runtime input flows, 1 = g_flowA, 2 = g_flowB
__device__ __forceinline__ const float* flow_sel(int sel, const float* flows) {
    return (sel == 0) ? flows : (sel == 1) ? (const float*)g_flowA : (const float*)g_flowB;
}

// ---------------------------------------------------------------------------
// Fused step kernel. Block-level specialization:
//   blockIdx.x <  IMG_BLKS : image compose (fp16 scratch, fp32 math)
//   blockIdx.x >= IMG_BLKS : flow compose (fp32, unchanged)
__global__ void __launch_bounds__(256) compose_step(int step, int finHWC,
    int imgPar, int flowSrcSel, int flowDstSel,
    const float* __restrict__ flows, float* __restrict__ outImg)
{
    int lp = blockIdx.y;
    int b  = blockIdx.z;
    int l  = step + lp;
    const float* srcFlow = flow_sel(flowSrcSel, flows);

    if (blockIdx.x >= IMG_BLKS) {
        // ---------------- flow path (fp32, verbatim R10) ----------------
        int pix = (blockIdx.x - IMG_BLKS) * 256 + threadIdx.x;

        const float* cf = srcFlow + (b * Lc + l) * (2 * HWc);
        float qfx = __ldg(cf + pix);
        float qfy = __ldg(cf + HWc + pix);

        float w00, w01, w10, w11; int o00, o01, o10, o11;
        grid_weights(pix, qfx, qfy, w00, w01, w10, w11, o00, o01, o10, o11);

        const float* pf = (lp == 0) ? (flows + (b * Lc) * (2 * HWc))
                       : (lp < step) ? ((const float*)g_flowF + (b * Lc + lp) * (2 * HWc))
                                     : (srcFlow + (b * Lc + lp) * (2 * HWc));
        float* dstFlow = (flowDstSel == 1) ? g_flowA : g_flowB;
        float* df = ((l < 2 * step) ? g_flowF : dstFlow) + (b * Lc + l) * (2 * HWc);

        float s0 = w00 * __ldg(pf + o00) + w01 * __ldg(pf + o01)
                 + w10 * __ldg(pf + o10) + w11 * __ldg(pf + o11);
        const float* pf1 = pf + HWc;
        float s1 = w00 * __ldg(pf1 + o00) + w01 * __ldg(pf1 + o01)
                 + w10 * __ldg(pf1 + o10) + w11 * __ldg(pf1 + o11);
        df[pix]       = qfx + s0;
        df[HWc + pix] = qfy + s1;
        return;
    }

    // ---------------- image path: warp = 8 px x 4 groups (8ch fp16/lane) ---
    __shared__ float sm[64 * 33];
    int t   = threadIdx.x;
    int c8  = t & 3;
    int pl  = t >> 2;                 // pixel-local 0..63
    int pix = blockIdx.x * 64 + pl;
    int co  = c8 * 8;                 // channel offset (halves)

    const __half* srcImg = (const __half*)(imgPar ? g_imgB4 : g_imgA4);
    __half*       dstImg = (__half*)(imgPar ? g_imgA4 : g_imgB4);

    const float* cf = srcFlow + (b * Lc + l) * (2 * HWc);
    float qfx = __ldg(cf + pix);
    float qfy = __ldg(cf + HWc + pix);

    float w00, w01, w10, w11; int o00, o01, o10, o11;
    grid_weights(pix, qfx, qfy, w00, w01, w10, w11, o00, o01, o10, o11);

    const __half* pi = ((lp == 0) ? (const __half*)g_imgA4
                      : (lp < step) ? (const __half*)g_imgF4 : srcImg)
                       + (b * Lc + lp) * IMG_SLICE_H;
    H8 t00, t01, t10, t11, cv8;
    t00.u = *(const uint4*)(pi + o00 * Cc + co);
    t01.u = *(const uint4*)(pi + o01 * Cc + co);
    t10.u = *(const uint4*)(pi + o10 * Cc + co);
    t11.u = *(const uint4*)(pi + o11 * Cc + co);

    int hwcOff = (b * Lc + l) * IMG_SLICE_H + pix * Cc + co;
    cv8.u = *(const uint4*)(srcImg + hwcOff);

    float r[8];
    #pragma unroll
    for (int k = 0; k < 4; k++) {
        float2 c  = __half22float2(cv8.h[k]);
        float2 a0 = __half22float2(t00.h[k]);
        float2 a1 = __half22float2(t01.h[k]);
        float2 a2 = __half22float2(t10.h[k]);
        float2 a3 = __half22float2(t11.h[k]);
        r[2*k]   = c.x + w00 * a0.x + w01 * a1.x + w10 * a2.x + w11 * a3.x;
        r[2*k+1] = c.y + w00 * a0.y + w01 * a1.y + w10 * a2.y + w11 * a3.y;
    }

    if (l < 2 * step) {                         // finalized (block-uniform)
        if (finHWC) {
            H8 ov;
            #pragma unroll
            for (int k = 0; k < 4; k++)
                ov.h[k] = __floats2half2_rn(r[2*k], r[2*k+1]);
            *(uint4*)((__half*)g_imgF4 + hwcOff) = ov.u;
        }
        int sb = pl * 33 + co;
        #pragma unroll
        for (int i = 0; i < 8; i++) sm[sb + i] = r[i];
        __syncthreads();
        int lane = t & 31, wp = t >> 5;
        float* oC = outImg + (b * Lc + l) * IMG_SLICE + blockIdx.x * 64;
        #pragma unroll
        for (int i = 0; i < 4; i++) {
            int ch = wp * 4 + i;
            __stcs(oC + ch * HWc + lane,      sm[lane * 33 + ch]);
            __stcs(oC + ch * HWc + lane + 32, sm[(lane + 32) * 33 + ch]);
        }
    } else {
        H8 ov;
        #pragma unroll
        for (int k = 0; k < 4; k++)
            ov.h[k] = __floats2half2_rn(r[2*k], r[2*k+1]);
        *(uint4*)(dstImg + hwcOff) = ov.u;
    }
}

// ---------------------------------------------------------------------------
extern "C" void kernel_launch(void* const* d_in, const int* in_sizes, int n_in,
                              void* d_out, int out_size) {
    const float* flows  = (const float*)d_in[0];
    const float* images = (const float*)d_in[1];
    if (n_in >= 2 && in_sizes[0] > in_sizes[1]) {
        const float* tmp = flows; flows = images; images = tmp;
    }
    float* out = (float*)d_out;

    // 1) transpose input images CHW(fp32) -> HWC(fp16) into g_imgA (+ slice0 -> d_out)
    t_chw2hwc<<<Bc * Lc * 256, 256>>>(images, out);

    // 2) log-scan, one fused launch per step (image blocks + flow blocks).
    int imgPar = 0;
    int flowSrc = 0;
    for (int s = 1; s < Lc; s <<= 1) {
        int Lp = Lc - s;
        int flowDst = (flowSrc == 2) ? 1 : 2;
        int doFlow = (s < 16) ? 1 : 0;   // last step's flow output never consumed
        int finHWC = (s < 16) ? 1 : 0;   // last step's finalized slices never re-gathered

        dim3 gi(IMG_BLKS + (doFlow ? FLOW_BLKS : 0), Lp, Bc);
        compose_step<<<gi, 256>>>(s, finHWC, imgPar, flowSrc, flowDst, flows, out);

        imgPar ^= 1;
        flowSrc = flowDst;
    }
}